// round 8
// baseline (speedup 1.0000x reference)
#include <cuda_runtime.h>

#define N_NODES 100000
#define HEADS 4
#define HIDDEN 32

// Scratch + precomputed coefficient storage (device globals: no allocation allowed).
// g_acc[h][n] = {Tx, Ty, Tz, S} where T = sum_e attn_h * rel_e, S = sum_e attn_h.
__device__ float4 g_acc[HEADS][N_NODES];
__device__ float  g_M[HEADS][3][3];       // quadratic form for scores (pre-scaled by 1/sqrt(32))
__device__ float  g_L[HEADS][3];          // linear term from biases
__device__ float  g_C[HEADS];             // constant term from biases
__device__ float  g_A[HEADS][3][HIDDEN];  // Wv_h^T @ Wout_h  contracted over d
__device__ float  g_U[HEADS][HIDDEN];     // bv_h @ Wout_h
__device__ int    g_is64;                 // 1 if edge_index is int64, 0 if int32

__global__ void detect_kernel(const void* __restrict__ ei_raw, int E) {
    // Interpret first 128 entries as int64. For a true-int64 buffer all are
    // valid node ids; for an int32 buffer the high word is the next random
    // index (nonzero w.p. 1-1e-5), so this misfires with prob ~0.
    const long long* p = (const long long*)ei_raw;
    int n = 2 * E < 128 ? 2 * E : 128;
    int ok = 1;
    for (int i = 0; i < n; i++) {
        long long v = p[i];
        if (v < 0 || v >= N_NODES) { ok = 0; break; }
    }
    g_is64 = ok;
}

__global__ void zero_kernel() {
    int idx = blockIdx.x * blockDim.x + threadIdx.x;
    int stride = gridDim.x * blockDim.x;
    float4* p = &g_acc[0][0];
    for (int i = idx; i < HEADS * N_NODES; i += stride)
        p[i] = make_float4(0.f, 0.f, 0.f, 0.f);
}

__global__ void precompute_kernel(const float* __restrict__ Wq, const float* __restrict__ bq,
                                  const float* __restrict__ Wk, const float* __restrict__ bk,
                                  const float* __restrict__ Wv, const float* __restrict__ bv,
                                  const float* __restrict__ Wout) {
    const float scale = rsqrtf((float)HIDDEN);
    int t = threadIdx.x;
    if (t < 36) {
        // M[h][i][j] = scale * sum_d Wq[i, h*32+d] * Wk[j, h*32+d]
        int h = t / 9, i = (t % 9) / 3, j = t % 3;
        float s = 0.f;
        for (int d = 0; d < HIDDEN; d++)
            s += Wq[i * 128 + h * 32 + d] * Wk[j * 128 + h * 32 + d];
        g_M[h][i][j] = s * scale;
    } else if (t < 48) {
        int u = t - 36; int h = u / 3, i = u % 3;
        float s = 0.f;
        for (int d = 0; d < HIDDEN; d++)
            s += Wq[i * 128 + h * 32 + d] * bk[h * 32 + d]
               + Wk[i * 128 + h * 32 + d] * bq[h * 32 + d];
        g_L[h][i] = s * scale;
    } else if (t < 52) {
        int h = t - 48;
        float s = 0.f;
        for (int d = 0; d < HIDDEN; d++) s += bq[h * 32 + d] * bk[h * 32 + d];
        g_C[h] = s * scale;
    } else if (t < 436) {
        // A[h][i][m] = sum_d Wv[i, h*32+d] * Wout[h*32+d, m]
        int u = t - 52; int h = u / 96; int r = u % 96; int i = r / 32, m = r % 32;
        float s = 0.f;
        for (int d = 0; d < HIDDEN; d++)
            s += Wv[i * 128 + h * 32 + d] * Wout[(h * 32 + d) * 32 + m];
        g_A[h][i][m] = s;
    } else if (t < 564) {
        int u = t - 436; int h = u / 32, m = u % 32;
        float s = 0.f;
        for (int d = 0; d < HIDDEN; d++)
            s += bv[h * 32 + d] * Wout[(h * 32 + d) * 32 + m];
        g_U[h][m] = s;
    }
}

__global__ void edge_kernel(const float* __restrict__ pos,
                            const void* __restrict__ ei_raw, int E) {
    int e = blockIdx.x * blockDim.x + threadIdx.x;
    if (e >= E) return;

    int r, c;
    if (g_is64) {
        const long long* ei = (const long long*)ei_raw;
        r = (int)ei[e];
        c = (int)ei[E + e];
    } else {
        const int* ei = (const int*)ei_raw;
        r = ei[e];
        c = ei[E + e];
    }

    float rx = __ldg(&pos[3 * r + 0]) - __ldg(&pos[3 * c + 0]);
    float ry = __ldg(&pos[3 * r + 1]) - __ldg(&pos[3 * c + 1]);
    float rz = __ldg(&pos[3 * r + 2]) - __ldg(&pos[3 * c + 2]);

    float sc[HEADS];
#pragma unroll
    for (int h = 0; h < HEADS; h++) {
        float qx = rx * g_M[h][0][0] + ry * g_M[h][1][0] + rz * g_M[h][2][0];
        float qy = rx * g_M[h][0][1] + ry * g_M[h][1][1] + rz * g_M[h][2][1];
        float qz = rx * g_M[h][0][2] + ry * g_M[h][1][2] + rz * g_M[h][2][2];
        sc[h] = rx * qx + ry * qy + rz * qz
              + rx * g_L[h][0] + ry * g_L[h][1] + rz * g_L[h][2] + g_C[h];
    }
    float mx = fmaxf(fmaxf(sc[0], sc[1]), fmaxf(sc[2], sc[3]));
    float ex[HEADS];
    float sum = 0.f;
#pragma unroll
    for (int h = 0; h < HEADS; h++) { ex[h] = __expf(sc[h] - mx); sum += ex[h]; }
    float inv = 1.f / sum;

#pragma unroll
    for (int h = 0; h < HEADS; h++) {
        float a = ex[h] * inv;
        float4* p = &g_acc[h][c];
        asm volatile("red.global.add.v4.f32 [%0], {%1, %2, %3, %4};"
                     :: "l"(p), "f"(a * rx), "f"(a * ry), "f"(a * rz), "f"(a)
                     : "memory");
    }
}

__global__ void node_kernel(const float* __restrict__ bout, const float* __restrict__ gamma,
                            const float* __restrict__ beta, float* __restrict__ out) {
    int gtid = blockIdx.x * blockDim.x + threadIdx.x;
    int n = gtid >> 5;
    int lane = gtid & 31;
    if (n >= N_NODES) return;

    float4 t0 = g_acc[0][n];
    float4 t1 = g_acc[1][n];
    float4 t2 = g_acc[2][n];
    float4 t3 = g_acc[3][n];
    // count = sum over edges of (sum_h attn_h) = sum_h S_h (softmax sums to 1 per edge)
    float cnt = t0.w + t1.w + t2.w + t3.w;
    float invc = 1.f / fmaxf(cnt, 1.f);

    float acc =
          t0.x * g_A[0][0][lane] + t0.y * g_A[0][1][lane] + t0.z * g_A[0][2][lane] + t0.w * g_U[0][lane]
        + t1.x * g_A[1][0][lane] + t1.y * g_A[1][1][lane] + t1.z * g_A[1][2][lane] + t1.w * g_U[1][lane]
        + t2.x * g_A[2][0][lane] + t2.y * g_A[2][1][lane] + t2.z * g_A[2][2][lane] + t2.w * g_U[2][lane]
        + t3.x * g_A[3][0][lane] + t3.y * g_A[3][1][lane] + t3.z * g_A[3][2][lane] + t3.w * g_U[3][lane];

    float val = acc * invc + bout[lane];

    // LayerNorm over 32 lanes (population variance, matching jnp.var)
    float s = val, ss = val * val;
#pragma unroll
    for (int o = 16; o > 0; o >>= 1) {
        s  += __shfl_xor_sync(0xffffffffu, s, o);
        ss += __shfl_xor_sync(0xffffffffu, ss, o);
    }
    float mu  = s * (1.f / 32.f);
    float var = ss * (1.f / 32.f) - mu * mu;
    float y = (val - mu) * rsqrtf(var + 1e-5f) * gamma[lane] + beta[lane];
    // SiLU
    out[n * 32 + lane] = y * (1.f / (1.f + __expf(-y)));
}

extern "C" void kernel_launch(void* const* d_in, const int* in_sizes, int n_in,
                              void* d_out, int out_size) {
    const float* pos   = (const float*)d_in[0];
    const void*  ei    = d_in[1];
    const float* Wq    = (const float*)d_in[2];
    const float* bq    = (const float*)d_in[3];
    const float* Wk    = (const float*)d_in[4];
    const float* bk    = (const float*)d_in[5];
    const float* Wv    = (const float*)d_in[6];
    const float* bv    = (const float*)d_in[7];
    const float* Wout  = (const float*)d_in[8];
    const float* bout  = (const float*)d_in[9];
    const float* gamma = (const float*)d_in[10];
    const float* beta  = (const float*)d_in[11];
    float* out = (float*)d_out;

    int E = in_sizes[1] / 2;

    detect_kernel<<<1, 1>>>(ei, E);
    zero_kernel<<<592, 256>>>();
    precompute_kernel<<<1, 576>>>(Wq, bq, Wk, bk, Wv, bv, Wout);
    edge_kernel<<<(E + 255) / 256, 256>>>(pos, ei, E);
    node_kernel<<<(N_NODES * 32 + 255) / 256, 256>>>(bout, gamma, beta, out);
}